// round 10
// baseline (speedup 1.0000x reference)
#include <cuda_runtime.h>
#include <cuda_bf16.h>
#include <cstdint>

// Segmented layer norm — persistent CTAs, double-buffered TMA prefetch.
// inputs: [0] input f32 [N,64], [1] offsets i32 [S] (cumulative ends),
//         [2] weight f32 [64], [3] bias f32 [64] ; output f32 [N,64]
//
// grid = #SMs, 1 CTA/SM, TPB=512. Each CTA loops over segments
// s = bid, bid+grid, ... with TWO smem buffers (436 rows = 111616B each):
// while computing segment i from buffer A, the cp.async.bulk for segment i+1
// into buffer B is in flight, so the HBM read stream never pauses.
// Per segment: pass 1 sum/sumsq from smem (shuffle + smem atomicAdd reduce),
// fold a=w*rstd, b=bias-mean*a, pass 2 normalize + STG.
// CAP=436 rows is +11 sigma over the 256±16 segment length; LDG fallback kept.

#define TPB 512
#define CAP_ROWS 436              // per-buffer rows; 2 x 111616 B = 223232 B
#define EPS 1e-5f

extern __shared__ float4 s_cache[];   // [2 * CAP_ROWS * 16]

__device__ __forceinline__ uint32_t smem_u32(const void* p) {
    uint32_t a;
    asm("{ .reg .u64 t; cvta.to.shared.u64 t, %1; cvt.u32.u64 %0, t; }"
        : "=r"(a) : "l"(p));
    return a;
}

__device__ __forceinline__ void mbar_wait(uint32_t mbar, uint32_t parity) {
    uint32_t done = 0;
    while (!done) {
        asm volatile(
            "{ .reg .pred p;\n"
            "  mbarrier.try_wait.parity.acquire.cta.shared::cta.b64 p, [%1], %2, 0x989680;\n"
            "  selp.b32 %0, 1, 0, p; }"
            : "=r"(done) : "r"(mbar), "r"(parity) : "memory");
    }
}

__device__ __forceinline__ void issue_copy(uint32_t mbar, uint32_t smem_dst,
                                           const float4* src, uint32_t bytes) {
    asm volatile("mbarrier.arrive.expect_tx.shared.b64 _, [%0], %1;"
                 :: "r"(mbar), "r"(bytes) : "memory");
    asm volatile(
        "cp.async.bulk.shared::cluster.global.mbarrier::complete_tx::bytes "
        "[%0], [%1], %2, [%3];"
        :: "r"(smem_dst), "l"(src), "r"(bytes), "r"(mbar) : "memory");
}

__global__ __launch_bounds__(TPB, 1) void seg_ln_kernel(
    const float* __restrict__ x,
    const int*   __restrict__ offsets,
    const float* __restrict__ weight,
    const float* __restrict__ bias,
    float*       __restrict__ out,
    int S)
{
    const int bid  = blockIdx.x;
    const int grid = gridDim.x;
    const int t    = threadIdx.x;

    __shared__ float sm_sum[64];
    __shared__ float sm_sq [64];
    __shared__ float sm_a[64];
    __shared__ float sm_b[64];
    __shared__ uint64_t sm_mbar[2];

    const int chunk = t & 15;     // float4 chunk within the 64-float row
    const int rgrp  = t >> 4;     // row offset within a 32-row group (0..31)
    const int lane  = t & 31;

    const float4* __restrict__ xv = reinterpret_cast<const float4*>(x);
    float4*       __restrict__ ov = reinterpret_cast<float4*>(out);

    const uint32_t mbar0 = smem_u32(&sm_mbar[0]);
    const uint32_t mbar1 = smem_u32(&sm_mbar[1]);
    const uint32_t cb0 = smem_u32(s_cache);
    const uint32_t cb1 = cb0 + (uint32_t)CAP_ROWS * 256u;

    // ---- One-time init ----
    if (t < 64) { sm_sum[t] = 0.f; sm_sq[t] = 0.f; }
    if (t == 0) {
        asm volatile("mbarrier.init.shared.b64 [%0], %1;"
                     :: "r"(mbar0), "r"(1) : "memory");
        asm volatile("mbarrier.init.shared.b64 [%0], %1;"
                     :: "r"(mbar1), "r"(1) : "memory");
    }
    __syncthreads();

    // ---- Prologue: prefetch first two segments ----
    if (t == 0) {
        if (bid < S) {
            const int st = (bid == 0) ? 0 : __ldg(&offsets[bid - 1]);
            const int en = __ldg(&offsets[bid]);
            const int cr = min(en - st, CAP_ROWS);
            issue_copy(mbar0, cb0, xv + (size_t)st * 16, (uint32_t)cr * 256u);
        }
        const int s1 = bid + grid;
        if (s1 < S) {
            const int st = __ldg(&offsets[s1 - 1]);
            const int en = __ldg(&offsets[s1]);
            const int cr = min(en - st, CAP_ROWS);
            issue_copy(mbar1, cb1, xv + (size_t)st * 16, (uint32_t)cr * 256u);
        }
    }

    uint32_t ph0 = 0, ph1 = 0;

    // ---- Main persistent loop ----
    for (int s = bid, k = 0; s < S; s += grid, ++k) {
        const int b = k & 1;
        const uint32_t mbar = b ? mbar1 : mbar0;
        const float4* buf = s_cache + (size_t)b * CAP_ROWS * 16;

        const int start = (s == 0) ? 0 : __ldg(&offsets[s - 1]);
        const int end   = __ldg(&offsets[s]);
        const int len   = end - start;
        const int crows = (len < CAP_ROWS) ? len : CAP_ROWS;

        // Wait for this buffer's copy
        if (b) { mbar_wait(mbar, ph1); ph1 ^= 1; }
        else   { mbar_wait(mbar, ph0); ph0 ^= 1; }

        // ---- Pass 1: per-feature sum / sumsq from smem ----
        float4 acc  = make_float4(0.f, 0.f, 0.f, 0.f);
        float4 accq = make_float4(0.f, 0.f, 0.f, 0.f);

        int r = rgrp;
        for (; r + 32 < crows; r += 64) {
            float4 v0 = buf[(r     ) * 16 + chunk];
            float4 v1 = buf[(r + 32) * 16 + chunk];
            acc.x += v0.x + v1.x; acc.y += v0.y + v1.y;
            acc.z += v0.z + v1.z; acc.w += v0.w + v1.w;
            accq.x = fmaf(v0.x, v0.x, fmaf(v1.x, v1.x, accq.x));
            accq.y = fmaf(v0.y, v0.y, fmaf(v1.y, v1.y, accq.y));
            accq.z = fmaf(v0.z, v0.z, fmaf(v1.z, v1.z, accq.z));
            accq.w = fmaf(v0.w, v0.w, fmaf(v1.w, v1.w, accq.w));
        }
        if (r < crows) {
            float4 v = buf[r * 16 + chunk];
            acc.x += v.x; acc.y += v.y; acc.z += v.z; acc.w += v.w;
            accq.x = fmaf(v.x, v.x, accq.x); accq.y = fmaf(v.y, v.y, accq.y);
            accq.z = fmaf(v.z, v.z, accq.z); accq.w = fmaf(v.w, v.w, accq.w);
        }
        // Overflow tail (CAP=436 is +11 sigma; effectively never taken)
        for (int rr = CAP_ROWS + rgrp; rr < len; rr += 32) {
            float4 v = __ldg(&xv[(size_t)(start + rr) * 16 + chunk]);
            acc.x += v.x; acc.y += v.y; acc.z += v.z; acc.w += v.w;
            accq.x = fmaf(v.x, v.x, accq.x); accq.y = fmaf(v.y, v.y, accq.y);
            accq.z = fmaf(v.z, v.z, accq.z); accq.w = fmaf(v.w, v.w, accq.w);
        }

        // ---- Warp fold + smem atomic reduce ----
        acc.x  += __shfl_xor_sync(0xffffffffu, acc.x,  16);
        acc.y  += __shfl_xor_sync(0xffffffffu, acc.y,  16);
        acc.z  += __shfl_xor_sync(0xffffffffu, acc.z,  16);
        acc.w  += __shfl_xor_sync(0xffffffffu, acc.w,  16);
        accq.x += __shfl_xor_sync(0xffffffffu, accq.x, 16);
        accq.y += __shfl_xor_sync(0xffffffffu, accq.y, 16);
        accq.z += __shfl_xor_sync(0xffffffffu, accq.z, 16);
        accq.w += __shfl_xor_sync(0xffffffffu, accq.w, 16);
        if (lane < 16) {
            atomicAdd(&sm_sum[chunk * 4 + 0], acc.x);
            atomicAdd(&sm_sum[chunk * 4 + 1], acc.y);
            atomicAdd(&sm_sum[chunk * 4 + 2], acc.z);
            atomicAdd(&sm_sum[chunk * 4 + 3], acc.w);
            atomicAdd(&sm_sq [chunk * 4 + 0], accq.x);
            atomicAdd(&sm_sq [chunk * 4 + 1], accq.y);
            atomicAdd(&sm_sq [chunk * 4 + 2], accq.z);
            atomicAdd(&sm_sq [chunk * 4 + 3], accq.w);
        }
        __syncthreads();

        // ---- Fold scale/shift; zero accumulators for next iteration ----
        if (t < 64) {
            const float inv  = 1.0f / (float)len;
            const float mean = sm_sum[t] * inv;
            float var = sm_sq[t] * inv - mean * mean;
            var = fmaxf(var, 0.0f);
            const float rstd = rsqrtf(var + EPS);
            const float a = weight[t] * rstd;
            sm_a[t] = a;
            sm_b[t] = bias[t] - mean * a;
            sm_sum[t] = 0.f;
            sm_sq [t] = 0.f;
        }
        __syncthreads();

        const float4 av = reinterpret_cast<const float4*>(sm_a)[chunk];
        const float4 bv = reinterpret_cast<const float4*>(sm_b)[chunk];

        // ---- Pass 2: normalize from smem, store ----
        r = rgrp;
        for (; r + 32 < crows; r += 64) {
            float4 v0 = buf[(r     ) * 16 + chunk];
            float4 v1 = buf[(r + 32) * 16 + chunk];
            float4 w0, w1;
            w0.x = fmaf(v0.x, av.x, bv.x); w0.y = fmaf(v0.y, av.y, bv.y);
            w0.z = fmaf(v0.z, av.z, bv.z); w0.w = fmaf(v0.w, av.w, bv.w);
            w1.x = fmaf(v1.x, av.x, bv.x); w1.y = fmaf(v1.y, av.y, bv.y);
            w1.z = fmaf(v1.z, av.z, bv.z); w1.w = fmaf(v1.w, av.w, bv.w);
            ov[(size_t)(start + r     ) * 16 + chunk] = w0;
            ov[(size_t)(start + r + 32) * 16 + chunk] = w1;
        }
        if (r < crows) {
            float4 v = buf[r * 16 + chunk];
            float4 w;
            w.x = fmaf(v.x, av.x, bv.x); w.y = fmaf(v.y, av.y, bv.y);
            w.z = fmaf(v.z, av.z, bv.z); w.w = fmaf(v.w, av.w, bv.w);
            ov[(size_t)(start + r) * 16 + chunk] = w;
        }
        for (int rr = CAP_ROWS + rgrp; rr < len; rr += 32) {
            float4 v = __ldg(&xv[(size_t)(start + rr) * 16 + chunk]);
            float4 w;
            w.x = fmaf(v.x, av.x, bv.x); w.y = fmaf(v.y, av.y, bv.y);
            w.z = fmaf(v.z, av.z, bv.z); w.w = fmaf(v.w, av.w, bv.w);
            ov[(size_t)(start + rr) * 16 + chunk] = w;
        }

        // All warps done reading buffer b -> safe to refill it
        __syncthreads();
        if (t == 0) {
            const int s2 = s + 2 * grid;
            if (s2 < S) {
                const int st = __ldg(&offsets[s2 - 1]);
                const int en = __ldg(&offsets[s2]);
                const int cr = min(en - st, CAP_ROWS);
                issue_copy(mbar, b ? cb1 : cb0,
                           xv + (size_t)st * 16, (uint32_t)cr * 256u);
            }
        }
    }
}

extern "C" void kernel_launch(void* const* d_in, const int* in_sizes, int n_in,
                              void* d_out, int out_size)
{
    const float* x       = (const float*)d_in[0];
    const int*   offsets = (const int*)  d_in[1];
    const float* weight  = (const float*)d_in[2];
    const float* bias    = (const float*)d_in[3];
    float*       out     = (float*)d_out;

    const int S = in_sizes[1];
    const int dyn_smem = 2 * CAP_ROWS * 16 * sizeof(float4);  // 223232 B

    int n_sm = 148;
    cudaDeviceGetAttribute(&n_sm, cudaDevAttrMultiProcessorCount, 0);

    cudaFuncSetAttribute(seg_ln_kernel,
                         cudaFuncAttributeMaxDynamicSharedMemorySize, dyn_smem);

    seg_ln_kernel<<<n_sm, TPB, dyn_smem>>>(x, offsets, weight, bias, out, S);
}

// round 11
// speedup vs baseline: 1.1477x; 1.1477x over previous
#include <cuda_runtime.h>
#include <cuda_bf16.h>
#include <cstdint>

// Segmented layer norm — TMA load + TMA bulk store, 3 CTAs/SM.
// inputs: [0] input f32 [N,64], [1] offsets i32 [S] (cumulative ends),
//         [2] weight f32 [64], [3] bias f32 [64] ; output f32 [N,64]
//
// One CTA per segment (S=8192). cp.async.bulk streams the segment (<=280 rows
// = 70KB) HBM->smem via mbarrier. Pass 1: per-feature sum/sumsq from smem,
// shuffle fold + smem atomicAdd reduce. Pass 2 normalizes IN PLACE in smem
// (LDS->FMA->STS), then ONE cp.async.bulk.global.shared::cta pushes the whole
// segment out via the TMA engine (write stream decoupled from warp issue).
// Thread 0 holds wait_group 0 so smem stays alive until the store drains.
// Rare >280-row overflow rows use an LDG/STG fallback. TPB=384, 3 CTAs/SM.

#define TPB 384
#define CAP_ROWS 280              // 280 rows * 256B = 71680 B dynamic smem
#define EPS 1e-5f

extern __shared__ float4 s_cache[];   // [CAP_ROWS * 16]

__device__ __forceinline__ uint32_t smem_u32(const void* p) {
    uint32_t a;
    asm("{ .reg .u64 t; cvta.to.shared.u64 t, %1; cvt.u32.u64 %0, t; }"
        : "=r"(a) : "l"(p));
    return a;
}

__global__ __launch_bounds__(TPB, 3) void seg_ln_kernel(
    const float* __restrict__ x,
    const int*   __restrict__ offsets,
    const float* __restrict__ weight,
    const float* __restrict__ bias,
    float*       __restrict__ out)
{
    const int s = blockIdx.x;
    const int t = threadIdx.x;

    const int start = (s == 0) ? 0 : offsets[s - 1];
    const int end   = offsets[s];
    const int len   = end - start;
    const int crows = (len < CAP_ROWS) ? len : CAP_ROWS;

    __shared__ float sm_sum[64];
    __shared__ float sm_sq [64];
    __shared__ float sm_a[64];
    __shared__ float sm_b[64];
    __shared__ uint64_t sm_mbar;

    const int chunk = t & 15;     // float4 chunk within the 64-float row
    const int rgrp  = t >> 4;     // row offset within a 24-row group (0..23)
    const int lane  = t & 31;

    const float4* __restrict__ xv = reinterpret_cast<const float4*>(x);
    float4*       __restrict__ ov = reinterpret_cast<float4*>(out);

    const uint32_t mbar = smem_u32(&sm_mbar);
    const uint32_t cache_base = smem_u32(s_cache);
    const uint32_t bytes = (uint32_t)crows * 256u;

    // ---- Init: zero accumulators, init mbarrier ----
    if (t < 64) { sm_sum[t] = 0.f; sm_sq[t] = 0.f; }
    if (t == 0) {
        asm volatile("mbarrier.init.shared.b64 [%0], %1;"
                     :: "r"(mbar), "r"(1) : "memory");
    }
    __syncthreads();

    // ---- Issue one bulk async copy for the whole cached segment ----
    if (t == 0) {
        asm volatile("mbarrier.arrive.expect_tx.shared.b64 _, [%0], %1;"
                     :: "r"(mbar), "r"(bytes) : "memory");
        asm volatile(
            "cp.async.bulk.shared::cluster.global.mbarrier::complete_tx::bytes "
            "[%0], [%1], %2, [%3];"
            :: "r"(cache_base), "l"(xv + (size_t)start * 16), "r"(bytes),
               "r"(mbar) : "memory");
    }

    // ---- Wait for the copy (acquire orders following LDS) ----
    {
        uint32_t done = 0;
        while (!done) {
            asm volatile(
                "{ .reg .pred p;\n"
                "  mbarrier.try_wait.parity.acquire.cta.shared::cta.b64 p, [%1], %2, 0x989680;\n"
                "  selp.b32 %0, 1, 0, p; }"
                : "=r"(done) : "r"(mbar), "r"(0u) : "memory");
        }
    }

    // ---- Pass 1: per-feature sum / sumsq from smem ----
    float4 acc  = make_float4(0.f, 0.f, 0.f, 0.f);
    float4 accq = make_float4(0.f, 0.f, 0.f, 0.f);

    int r = rgrp;
    for (; r + 24 < crows; r += 48) {
        float4 v0 = s_cache[(r     ) * 16 + chunk];
        float4 v1 = s_cache[(r + 24) * 16 + chunk];
        acc.x += v0.x + v1.x; acc.y += v0.y + v1.y;
        acc.z += v0.z + v1.z; acc.w += v0.w + v1.w;
        accq.x = fmaf(v0.x, v0.x, fmaf(v1.x, v1.x, accq.x));
        accq.y = fmaf(v0.y, v0.y, fmaf(v1.y, v1.y, accq.y));
        accq.z = fmaf(v0.z, v0.z, fmaf(v1.z, v1.z, accq.z));
        accq.w = fmaf(v0.w, v0.w, fmaf(v1.w, v1.w, accq.w));
    }
    if (r < crows) {
        float4 v = s_cache[r * 16 + chunk];
        acc.x += v.x; acc.y += v.y; acc.z += v.z; acc.w += v.w;
        accq.x = fmaf(v.x, v.x, accq.x); accq.y = fmaf(v.y, v.y, accq.y);
        accq.z = fmaf(v.z, v.z, accq.z); accq.w = fmaf(v.w, v.w, accq.w);
    }
    // Overflow tail (rare: ~7% of segments, a few rows; correctness guard)
    for (int rr = CAP_ROWS + rgrp; rr < len; rr += 24) {
        float4 v = __ldg(&xv[(size_t)(start + rr) * 16 + chunk]);
        acc.x += v.x; acc.y += v.y; acc.z += v.z; acc.w += v.w;
        accq.x = fmaf(v.x, v.x, accq.x); accq.y = fmaf(v.y, v.y, accq.y);
        accq.z = fmaf(v.z, v.z, accq.z); accq.w = fmaf(v.w, v.w, accq.w);
    }

    // ---- Warp fold (lanes L, L^16 share chunk), then smem atomic reduce ----
    acc.x  += __shfl_xor_sync(0xffffffffu, acc.x,  16);
    acc.y  += __shfl_xor_sync(0xffffffffu, acc.y,  16);
    acc.z  += __shfl_xor_sync(0xffffffffu, acc.z,  16);
    acc.w  += __shfl_xor_sync(0xffffffffu, acc.w,  16);
    accq.x += __shfl_xor_sync(0xffffffffu, accq.x, 16);
    accq.y += __shfl_xor_sync(0xffffffffu, accq.y, 16);
    accq.z += __shfl_xor_sync(0xffffffffu, accq.z, 16);
    accq.w += __shfl_xor_sync(0xffffffffu, accq.w, 16);
    if (lane < 16) {
        atomicAdd(&sm_sum[chunk * 4 + 0], acc.x);
        atomicAdd(&sm_sum[chunk * 4 + 1], acc.y);
        atomicAdd(&sm_sum[chunk * 4 + 2], acc.z);
        atomicAdd(&sm_sum[chunk * 4 + 3], acc.w);
        atomicAdd(&sm_sq [chunk * 4 + 0], accq.x);
        atomicAdd(&sm_sq [chunk * 4 + 1], accq.y);
        atomicAdd(&sm_sq [chunk * 4 + 2], accq.z);
        atomicAdd(&sm_sq [chunk * 4 + 3], accq.w);
    }
    __syncthreads();

    // ---- Fold scale/shift per feature ----
    if (t < 64) {
        const float inv  = 1.0f / (float)len;
        const float mean = sm_sum[t] * inv;
        float var = sm_sq[t] * inv - mean * mean;
        var = fmaxf(var, 0.0f);
        const float rstd = rsqrtf(var + EPS);
        const float a = weight[t] * rstd;
        sm_a[t] = a;
        sm_b[t] = bias[t] - mean * a;
    }
    __syncthreads();

    const float4 av = reinterpret_cast<const float4*>(sm_a)[chunk];
    const float4 bv = reinterpret_cast<const float4*>(sm_b)[chunk];

    // ---- Pass 2: normalize IN PLACE in smem ----
    r = rgrp;
    for (; r + 24 < crows; r += 48) {
        float4 v0 = s_cache[(r     ) * 16 + chunk];
        float4 v1 = s_cache[(r + 24) * 16 + chunk];
        float4 w0, w1;
        w0.x = fmaf(v0.x, av.x, bv.x); w0.y = fmaf(v0.y, av.y, bv.y);
        w0.z = fmaf(v0.z, av.z, bv.z); w0.w = fmaf(v0.w, av.w, bv.w);
        w1.x = fmaf(v1.x, av.x, bv.x); w1.y = fmaf(v1.y, av.y, bv.y);
        w1.z = fmaf(v1.z, av.z, bv.z); w1.w = fmaf(v1.w, av.w, bv.w);
        s_cache[(r     ) * 16 + chunk] = w0;
        s_cache[(r + 24) * 16 + chunk] = w1;
    }
    if (r < crows) {
        float4 v = s_cache[r * 16 + chunk];
        float4 w;
        w.x = fmaf(v.x, av.x, bv.x); w.y = fmaf(v.y, av.y, bv.y);
        w.z = fmaf(v.z, av.z, bv.z); w.w = fmaf(v.w, av.w, bv.w);
        s_cache[r * 16 + chunk] = w;
    }
    __syncthreads();

    // ---- Bulk store: one TMA transfer smem -> gmem for the whole segment ----
    if (t == 0) {
        asm volatile("fence.proxy.async.shared::cta;" ::: "memory");
        asm volatile(
            "cp.async.bulk.global.shared::cta.bulk_group [%0], [%1], %2;"
            :: "l"(ov + (size_t)start * 16), "r"(cache_base), "r"(bytes)
            : "memory");
        asm volatile("cp.async.bulk.commit_group;" ::: "memory");
    }

    // Overflow tail (rare): direct LDG->STG
    for (int rr = CAP_ROWS + rgrp; rr < len; rr += 24) {
        float4 v = __ldg(&xv[(size_t)(start + rr) * 16 + chunk]);
        float4 w;
        w.x = fmaf(v.x, av.x, bv.x); w.y = fmaf(v.y, av.y, bv.y);
        w.z = fmaf(v.z, av.z, bv.z); w.w = fmaf(v.w, av.w, bv.w);
        ov[(size_t)(start + rr) * 16 + chunk] = w;
    }

    // Thread 0 keeps the CTA (and its smem) alive until the store drains.
    if (t == 0) {
        asm volatile("cp.async.bulk.wait_group 0;" ::: "memory");
    }
}

extern "C" void kernel_launch(void* const* d_in, const int* in_sizes, int n_in,
                              void* d_out, int out_size)
{
    const float* x       = (const float*)d_in[0];
    const int*   offsets = (const int*)  d_in[1];
    const float* weight  = (const float*)d_in[2];
    const float* bias    = (const float*)d_in[3];
    float*       out     = (float*)d_out;

    const int S = in_sizes[1];
    const int dyn_smem = CAP_ROWS * 16 * sizeof(float4);  // 71680 B

    cudaFuncSetAttribute(seg_ln_kernel,
                         cudaFuncAttributeMaxDynamicSharedMemorySize, dyn_smem);

    seg_ln_kernel<<<S, TPB, dyn_smem>>>(x, offsets, weight, bias, out);
}

// round 13
// speedup vs baseline: 1.1555x; 1.0068x over previous
#include <cuda_runtime.h>
#include <cuda_bf16.h>
#include <cstdint>

// Segmented layer norm, TMA-cached single-read, 3 CTAs/SM (R9 + CAP 288).
// inputs: [0] input f32 [N,64], [1] offsets i32 [S] (cumulative ends),
//         [2] weight f32 [64], [3] bias f32 [64] ; output f32 [N,64]
//
// One CTA per segment (S=8192). One cp.async.bulk per CTA streams the segment
// (<=288 rows = 73728B) HBM->smem via mbarrier. Pass 1: per-feature sum/sumsq
// from smem, lane-fold + smem atomicAdd reduction (tiny static smem so THREE
// CTAs fit per SM for deep TMA/compute overlap). Pass 2 normalizes from smem
// and stores via STG. Rare >288-row overflow rows (~2% of segments) use an
// LDG fallback. TPB=384, 3 CTAs/SM (36 warps).

#define TPB 384
#define CAP_ROWS 288              // 288 rows * 256B = 73728 B dynamic smem
#define EPS 1e-5f

extern __shared__ float4 s_cache[];   // [CAP_ROWS * 16]

__device__ __forceinline__ uint32_t smem_u32(const void* p) {
    uint32_t a;
    asm("{ .reg .u64 t; cvta.to.shared.u64 t, %1; cvt.u32.u64 %0, t; }"
        : "=r"(a) : "l"(p));
    return a;
}

__global__ __launch_bounds__(TPB, 3) void seg_ln_kernel(
    const float* __restrict__ x,
    const int*   __restrict__ offsets,
    const float* __restrict__ weight,
    const float* __restrict__ bias,
    float*       __restrict__ out)
{
    const int s = blockIdx.x;
    const int t = threadIdx.x;

    const int start = (s == 0) ? 0 : offsets[s - 1];
    const int end   = offsets[s];
    const int len   = end - start;
    const int crows = (len < CAP_ROWS) ? len : CAP_ROWS;

    __shared__ float sm_sum[64];
    __shared__ float sm_sq [64];
    __shared__ float sm_a[64];
    __shared__ float sm_b[64];
    __shared__ uint64_t sm_mbar;

    const int chunk = t & 15;     // float4 chunk within the 64-float row
    const int rgrp  = t >> 4;     // row offset within a 24-row group (0..23)
    const int lane  = t & 31;

    const float4* __restrict__ xv = reinterpret_cast<const float4*>(x);
    float4*       __restrict__ ov = reinterpret_cast<float4*>(out);

    const uint32_t mbar = smem_u32(&sm_mbar);
    const uint32_t cache_base = smem_u32(s_cache);
    const uint32_t bytes = (uint32_t)crows * 256u;

    // ---- Init: zero accumulators, init mbarrier ----
    if (t < 64) { sm_sum[t] = 0.f; sm_sq[t] = 0.f; }
    if (t == 0) {
        asm volatile("mbarrier.init.shared.b64 [%0], %1;"
                     :: "r"(mbar), "r"(1) : "memory");
    }
    __syncthreads();

    // ---- Issue one bulk async copy for the whole cached segment ----
    if (t == 0) {
        asm volatile("mbarrier.arrive.expect_tx.shared.b64 _, [%0], %1;"
                     :: "r"(mbar), "r"(bytes) : "memory");
        asm volatile(
            "cp.async.bulk.shared::cluster.global.mbarrier::complete_tx::bytes "
            "[%0], [%1], %2, [%3];"
            :: "r"(cache_base), "l"(xv + (size_t)start * 16), "r"(bytes),
               "r"(mbar) : "memory");
    }

    // ---- Wait for the copy (acquire orders following LDS) ----
    {
        uint32_t done = 0;
        while (!done) {
            asm volatile(
                "{ .reg .pred p;\n"
                "  mbarrier.try_wait.parity.acquire.cta.shared::cta.b64 p, [%1], %2, 0x989680;\n"
                "  selp.b32 %0, 1, 0, p; }"
                : "=r"(done) : "r"(mbar), "r"(0u) : "memory");
        }
    }

    // ---- Pass 1: per-feature sum / sumsq from smem ----
    float4 acc  = make_float4(0.f, 0.f, 0.f, 0.f);
    float4 accq = make_float4(0.f, 0.f, 0.f, 0.f);

    int r = rgrp;
    for (; r + 24 < crows; r += 48) {
        float4 v0 = s_cache[(r     ) * 16 + chunk];
        float4 v1 = s_cache[(r + 24) * 16 + chunk];
        acc.x += v0.x + v1.x; acc.y += v0.y + v1.y;
        acc.z += v0.z + v1.z; acc.w += v0.w + v1.w;
        accq.x = fmaf(v0.x, v0.x, fmaf(v1.x, v1.x, accq.x));
        accq.y = fmaf(v0.y, v0.y, fmaf(v1.y, v1.y, accq.y));
        accq.z = fmaf(v0.z, v0.z, fmaf(v1.z, v1.z, accq.z));
        accq.w = fmaf(v0.w, v0.w, fmaf(v1.w, v1.w, accq.w));
    }
    if (r < crows) {
        float4 v = s_cache[r * 16 + chunk];
        acc.x += v.x; acc.y += v.y; acc.z += v.z; acc.w += v.w;
        accq.x = fmaf(v.x, v.x, accq.x); accq.y = fmaf(v.y, v.y, accq.y);
        accq.z = fmaf(v.z, v.z, accq.z); accq.w = fmaf(v.w, v.w, accq.w);
    }
    // Overflow tail (rare: ~2% of segments, a few rows; correctness guard)
    for (int rr = CAP_ROWS + rgrp; rr < len; rr += 24) {
        float4 v = __ldg(&xv[(size_t)(start + rr) * 16 + chunk]);
        acc.x += v.x; acc.y += v.y; acc.z += v.z; acc.w += v.w;
        accq.x = fmaf(v.x, v.x, accq.x); accq.y = fmaf(v.y, v.y, accq.y);
        accq.z = fmaf(v.z, v.z, accq.z); accq.w = fmaf(v.w, v.w, accq.w);
    }

    // ---- Warp fold (lanes L, L^16 share chunk), then smem atomic reduce ----
    acc.x  += __shfl_xor_sync(0xffffffffu, acc.x,  16);
    acc.y  += __shfl_xor_sync(0xffffffffu, acc.y,  16);
    acc.z  += __shfl_xor_sync(0xffffffffu, acc.z,  16);
    acc.w  += __shfl_xor_sync(0xffffffffu, acc.w,  16);
    accq.x += __shfl_xor_sync(0xffffffffu, accq.x, 16);
    accq.y += __shfl_xor_sync(0xffffffffu, accq.y, 16);
    accq.z += __shfl_xor_sync(0xffffffffu, accq.z, 16);
    accq.w += __shfl_xor_sync(0xffffffffu, accq.w, 16);
    if (lane < 16) {
        atomicAdd(&sm_sum[chunk * 4 + 0], acc.x);
        atomicAdd(&sm_sum[chunk * 4 + 1], acc.y);
        atomicAdd(&sm_sum[chunk * 4 + 2], acc.z);
        atomicAdd(&sm_sum[chunk * 4 + 3], acc.w);
        atomicAdd(&sm_sq [chunk * 4 + 0], accq.x);
        atomicAdd(&sm_sq [chunk * 4 + 1], accq.y);
        atomicAdd(&sm_sq [chunk * 4 + 2], accq.z);
        atomicAdd(&sm_sq [chunk * 4 + 3], accq.w);
    }
    __syncthreads();

    // ---- Fold scale/shift per feature ----
    if (t < 64) {
        const float inv  = 1.0f / (float)len;
        const float mean = sm_sum[t] * inv;
        float var = sm_sq[t] * inv - mean * mean;
        var = fmaxf(var, 0.0f);
        const float rstd = rsqrtf(var + EPS);
        const float a = weight[t] * rstd;
        sm_a[t] = a;
        sm_b[t] = bias[t] - mean * a;
    }
    __syncthreads();

    const float4 av = reinterpret_cast<const float4*>(sm_a)[chunk];
    const float4 bv = reinterpret_cast<const float4*>(sm_b)[chunk];

    // ---- Pass 2: normalize from smem, store via STG ----
    r = rgrp;
    for (; r + 24 < crows; r += 48) {
        float4 v0 = s_cache[(r     ) * 16 + chunk];
        float4 v1 = s_cache[(r + 24) * 16 + chunk];
        float4 w0, w1;
        w0.x = fmaf(v0.x, av.x, bv.x); w0.y = fmaf(v0.y, av.y, bv.y);
        w0.z = fmaf(v0.z, av.z, bv.z); w0.w = fmaf(v0.w, av.w, bv.w);
        w1.x = fmaf(v1.x, av.x, bv.x); w1.y = fmaf(v1.y, av.y, bv.y);
        w1.z = fmaf(v1.z, av.z, bv.z); w1.w = fmaf(v1.w, av.w, bv.w);
        ov[(size_t)(start + r     ) * 16 + chunk] = w0;
        ov[(size_t)(start + r + 24) * 16 + chunk] = w1;
    }
    if (r < crows) {
        float4 v = s_cache[r * 16 + chunk];
        float4 w;
        w.x = fmaf(v.x, av.x, bv.x); w.y = fmaf(v.y, av.y, bv.y);
        w.z = fmaf(v.z, av.z, bv.z); w.w = fmaf(v.w, av.w, bv.w);
        ov[(size_t)(start + r) * 16 + chunk] = w;
    }
    // Overflow tail (rare)
    for (int rr = CAP_ROWS + rgrp; rr < len; rr += 24) {
        float4 v = __ldg(&xv[(size_t)(start + rr) * 16 + chunk]);
        float4 w;
        w.x = fmaf(v.x, av.x, bv.x); w.y = fmaf(v.y, av.y, bv.y);
        w.z = fmaf(v.z, av.z, bv.z); w.w = fmaf(v.w, av.w, bv.w);
        ov[(size_t)(start + rr) * 16 + chunk] = w;
    }
}

extern "C" void kernel_launch(void* const* d_in, const int* in_sizes, int n_in,
                              void* d_out, int out_size)
{
    const float* x       = (const float*)d_in[0];
    const int*   offsets = (const int*)  d_in[1];
    const float* weight  = (const float*)d_in[2];
    const float* bias    = (const float*)d_in[3];
    float*       out     = (float*)d_out;

    const int S = in_sizes[1];
    const int dyn_smem = CAP_ROWS * 16 * sizeof(float4);  // 73728 B

    cudaFuncSetAttribute(seg_ln_kernel,
                         cudaFuncAttributeMaxDynamicSharedMemorySize, dyn_smem);

    seg_ln_kernel<<<S, TPB, dyn_smem>>>(x, offsets, weight, bias, out);
}

// round 14
// speedup vs baseline: 1.1676x; 1.0105x over previous
#include <cuda_runtime.h>
#include <cuda_bf16.h>
#include <cstdint>

// Segmented layer norm, TMA-cached single-read, 3 CTAs/SM, streaming hints.
// inputs: [0] input f32 [N,64], [1] offsets i32 [S] (cumulative ends),
//         [2] weight f32 [64], [3] bias f32 [64] ; output f32 [N,64]
//
// One CTA per segment (S=8192). One cp.async.bulk per CTA (with L2
// evict-first policy: read lines are single-use) streams the segment
// (<=288 rows = 73728B) HBM->smem via mbarrier. Pass 1: per-feature sum/sumsq
// from smem, lane-fold + smem atomicAdd reduce. Pass 2 normalizes from smem
// and stores via st.global.cs (streaming, evict-first: written lines are
// never re-read). Rare >288-row overflow uses an LDG fallback.
// TPB=384, 3 CTAs/SM (36 warps).

#define TPB 384
#define CAP_ROWS 288              // 288 rows * 256B = 73728 B dynamic smem
#define EPS 1e-5f

extern __shared__ float4 s_cache[];   // [CAP_ROWS * 16]

__device__ __forceinline__ uint32_t smem_u32(const void* p) {
    uint32_t a;
    asm("{ .reg .u64 t; cvta.to.shared.u64 t, %1; cvt.u32.u64 %0, t; }"
        : "=r"(a) : "l"(p));
    return a;
}

__device__ __forceinline__ void stg_cs(float4* p, float4 v) {
    asm volatile("st.global.cs.v4.f32 [%0], {%1, %2, %3, %4};"
                 :: "l"(p), "f"(v.x), "f"(v.y), "f"(v.z), "f"(v.w)
                 : "memory");
}

__global__ __launch_bounds__(TPB, 3) void seg_ln_kernel(
    const float* __restrict__ x,
    const int*   __restrict__ offsets,
    const float* __restrict__ weight,
    const float* __restrict__ bias,
    float*       __restrict__ out)
{
    const int s = blockIdx.x;
    const int t = threadIdx.x;

    const int start = (s == 0) ? 0 : offsets[s - 1];
    const int end   = offsets[s];
    const int len   = end - start;
    const int crows = (len < CAP_ROWS) ? len : CAP_ROWS;

    __shared__ float sm_sum[64];
    __shared__ float sm_sq [64];
    __shared__ float sm_a[64];
    __shared__ float sm_b[64];
    __shared__ uint64_t sm_mbar;

    const int chunk = t & 15;     // float4 chunk within the 64-float row
    const int rgrp  = t >> 4;     // row offset within a 24-row group (0..23)
    const int lane  = t & 31;

    const float4* __restrict__ xv = reinterpret_cast<const float4*>(x);
    float4*       __restrict__ ov = reinterpret_cast<float4*>(out);

    const uint32_t mbar = smem_u32(&sm_mbar);
    const uint32_t cache_base = smem_u32(s_cache);
    const uint32_t bytes = (uint32_t)crows * 256u;

    // ---- Init: zero accumulators, init mbarrier ----
    if (t < 64) { sm_sum[t] = 0.f; sm_sq[t] = 0.f; }
    if (t == 0) {
        asm volatile("mbarrier.init.shared.b64 [%0], %1;"
                     :: "r"(mbar), "r"(1) : "memory");
    }
    __syncthreads();

    // ---- Issue one bulk async copy (L2 evict-first: single-use lines) ----
    if (t == 0) {
        asm volatile("mbarrier.arrive.expect_tx.shared.b64 _, [%0], %1;"
                     :: "r"(mbar), "r"(bytes) : "memory");
        asm volatile(
            "{ .reg .b64 pol;\n"
            "  createpolicy.fractional.L2::evict_first.b64 pol, 1.0;\n"
            "  cp.async.bulk.shared::cluster.global.mbarrier::complete_tx::bytes.L2::cache_hint "
            "[%0], [%1], %2, [%3], pol; }"
            :: "r"(cache_base), "l"(xv + (size_t)start * 16), "r"(bytes),
               "r"(mbar) : "memory");
    }

    // ---- Wait for the copy (acquire orders following LDS) ----
    {
        uint32_t done = 0;
        while (!done) {
            asm volatile(
                "{ .reg .pred p;\n"
                "  mbarrier.try_wait.parity.acquire.cta.shared::cta.b64 p, [%1], %2, 0x989680;\n"
                "  selp.b32 %0, 1, 0, p; }"
                : "=r"(done) : "r"(mbar), "r"(0u) : "memory");
        }
    }

    // ---- Pass 1: per-feature sum / sumsq from smem ----
    float4 acc  = make_float4(0.f, 0.f, 0.f, 0.f);
    float4 accq = make_float4(0.f, 0.f, 0.f, 0.f);

    int r = rgrp;
    for (; r + 24 < crows; r += 48) {
        float4 v0 = s_cache[(r     ) * 16 + chunk];
        float4 v1 = s_cache[(r + 24) * 16 + chunk];
        acc.x += v0.x + v1.x; acc.y += v0.y + v1.y;
        acc.z += v0.z + v1.z; acc.w += v0.w + v1.w;
        accq.x = fmaf(v0.x, v0.x, fmaf(v1.x, v1.x, accq.x));
        accq.y = fmaf(v0.y, v0.y, fmaf(v1.y, v1.y, accq.y));
        accq.z = fmaf(v0.z, v0.z, fmaf(v1.z, v1.z, accq.z));
        accq.w = fmaf(v0.w, v0.w, fmaf(v1.w, v1.w, accq.w));
    }
    if (r < crows) {
        float4 v = s_cache[r * 16 + chunk];
        acc.x += v.x; acc.y += v.y; acc.z += v.z; acc.w += v.w;
        accq.x = fmaf(v.x, v.x, accq.x); accq.y = fmaf(v.y, v.y, accq.y);
        accq.z = fmaf(v.z, v.z, accq.z); accq.w = fmaf(v.w, v.w, accq.w);
    }
    // Overflow tail (rare: ~2% of segments, a few rows; correctness guard)
    for (int rr = CAP_ROWS + rgrp; rr < len; rr += 24) {
        float4 v = __ldg(&xv[(size_t)(start + rr) * 16 + chunk]);
        acc.x += v.x; acc.y += v.y; acc.z += v.z; acc.w += v.w;
        accq.x = fmaf(v.x, v.x, accq.x); accq.y = fmaf(v.y, v.y, accq.y);
        accq.z = fmaf(v.z, v.z, accq.z); accq.w = fmaf(v.w, v.w, accq.w);
    }

    // ---- Warp fold (lanes L, L^16 share chunk), then smem atomic reduce ----
    acc.x  += __shfl_xor_sync(0xffffffffu, acc.x,  16);
    acc.y  += __shfl_xor_sync(0xffffffffu, acc.y,  16);
    acc.z  += __shfl_xor_sync(0xffffffffu, acc.z,  16);
    acc.w  += __shfl_xor_sync(0xffffffffu, acc.w,  16);
    accq.x += __shfl_xor_sync(0xffffffffu, accq.x, 16);
    accq.y += __shfl_xor_sync(0xffffffffu, accq.y, 16);
    accq.z += __shfl_xor_sync(0xffffffffu, accq.z, 16);
    accq.w += __shfl_xor_sync(0xffffffffu, accq.w, 16);
    if (lane < 16) {
        atomicAdd(&sm_sum[chunk * 4 + 0], acc.x);
        atomicAdd(&sm_sum[chunk * 4 + 1], acc.y);
        atomicAdd(&sm_sum[chunk * 4 + 2], acc.z);
        atomicAdd(&sm_sum[chunk * 4 + 3], acc.w);
        atomicAdd(&sm_sq [chunk * 4 + 0], accq.x);
        atomicAdd(&sm_sq [chunk * 4 + 1], accq.y);
        atomicAdd(&sm_sq [chunk * 4 + 2], accq.z);
        atomicAdd(&sm_sq [chunk * 4 + 3], accq.w);
    }
    __syncthreads();

    // ---- Fold scale/shift per feature ----
    if (t < 64) {
        const float inv  = 1.0f / (float)len;
        const float mean = sm_sum[t] * inv;
        float var = sm_sq[t] * inv - mean * mean;
        var = fmaxf(var, 0.0f);
        const float rstd = rsqrtf(var + EPS);
        const float a = weight[t] * rstd;
        sm_a[t] = a;
        sm_b[t] = bias[t] - mean * a;
    }
    __syncthreads();

    const float4 av = reinterpret_cast<const float4*>(sm_a)[chunk];
    const float4 bv = reinterpret_cast<const float4*>(sm_b)[chunk];

    // ---- Pass 2: normalize from smem, streaming stores ----
    r = rgrp;
    for (; r + 24 < crows; r += 48) {
        float4 v0 = s_cache[(r     ) * 16 + chunk];
        float4 v1 = s_cache[(r + 24) * 16 + chunk];
        float4 w0, w1;
        w0.x = fmaf(v0.x, av.x, bv.x); w0.y = fmaf(v0.y, av.y, bv.y);
        w0.z = fmaf(v0.z, av.z, bv.z); w0.w = fmaf(v0.w, av.w, bv.w);
        w1.x = fmaf(v1.x, av.x, bv.x); w1.y = fmaf(v1.y, av.y, bv.y);
        w1.z = fmaf(v1.z, av.z, bv.z); w1.w = fmaf(v1.w, av.w, bv.w);
        stg_cs(&ov[(size_t)(start + r     ) * 16 + chunk], w0);
        stg_cs(&ov[(size_t)(start + r + 24) * 16 + chunk], w1);
    }
    if (r < crows) {
        float4 v = s_cache[r * 16 + chunk];
        float4 w;
        w.x = fmaf(v.x, av.x, bv.x); w.y = fmaf(v.y, av.y, bv.y);
        w.z = fmaf(v.z, av.z, bv.z); w.w = fmaf(v.w, av.w, bv.w);
        stg_cs(&ov[(size_t)(start + r) * 16 + chunk], w);
    }
    // Overflow tail (rare)
    for (int rr = CAP_ROWS + rgrp; rr < len; rr += 24) {
        float4 v = __ldg(&xv[(size_t)(start + rr) * 16 + chunk]);
        float4 w;
        w.x = fmaf(v.x, av.x, bv.x); w.y = fmaf(v.y, av.y, bv.y);
        w.z = fmaf(v.z, av.z, bv.z); w.w = fmaf(v.w, av.w, bv.w);
        stg_cs(&ov[(size_t)(start + rr) * 16 + chunk], w);
    }
}

extern "C" void kernel_launch(void* const* d_in, const int* in_sizes, int n_in,
                              void* d_out, int out_size)
{
    const float* x       = (const float*)d_in[0];
    const int*   offsets = (const int*)  d_in[1];
    const float* weight  = (const float*)d_in[2];
    const float* bias    = (const float*)d_in[3];
    float*       out     = (float*)d_out;

    const int S = in_sizes[1];
    const int dyn_smem = CAP_ROWS * 16 * sizeof(float4);  // 73728 B

    cudaFuncSetAttribute(seg_ln_kernel,
                         cudaFuncAttributeMaxDynamicSharedMemorySize, dyn_smem);

    seg_ln_kernel<<<S, TPB, dyn_smem>>>(x, offsets, weight, bias, out);
}

// round 15
// speedup vs baseline: 1.1697x; 1.0018x over previous
#include <cuda_runtime.h>
#include <cuda_bf16.h>
#include <cstdint>

// Segmented layer norm — converged best (R14 family).
// inputs: [0] input f32 [N,64], [1] offsets i32 [S] (cumulative ends),
//         [2] weight f32 [64], [3] bias f32 [64] ; output f32 [N,64]
//
// One CTA per segment (S=8192). One cp.async.bulk per CTA (L2 evict-first:
// read lines are single-use) streams the segment (<=288 rows = 73728B)
// HBM->smem via mbarrier. Pass 1: per-feature sum/sumsq from smem, lane fold
// + smem atomicAdd reduce (tiny static smem -> 3 CTAs/SM for phase-staggered
// TMA/compute/store overlap). Pass 2 normalizes from smem, st.global.cs
// streaming stores. Rare >288-row overflow (~2% of segments) LDG fallback.
// TPB=384, 3 CTAs/SM (36 warps). Traffic = 1.02GB (floor); DRAM ~83% = this
// chip's measured mixed-stream ceiling for the pattern.

#define TPB 384
#define CAP_ROWS 288              // 288 rows * 256B = 73728 B dynamic smem
#define EPS 1e-5f

extern __shared__ float4 s_cache[];   // [CAP_ROWS * 16]

__device__ __forceinline__ uint32_t smem_u32(const void* p) {
    uint32_t a;
    asm("{ .reg .u64 t; cvta.to.shared.u64 t, %1; cvt.u32.u64 %0, t; }"
        : "=r"(a) : "l"(p));
    return a;
}

__device__ __forceinline__ void stg_cs(float4* p, float4 v) {
    asm volatile("st.global.cs.v4.f32 [%0], {%1, %2, %3, %4};"
                 :: "l"(p), "f"(v.x), "f"(v.y), "f"(v.z), "f"(v.w)
                 : "memory");
}

__global__ __launch_bounds__(TPB, 3) void seg_ln_kernel(
    const float* __restrict__ x,
    const int*   __restrict__ offsets,
    const float* __restrict__ weight,
    const float* __restrict__ bias,
    float*       __restrict__ out)
{
    const int s = blockIdx.x;
    const int t = threadIdx.x;

    const int start = (s == 0) ? 0 : offsets[s - 1];
    const int end   = offsets[s];
    const int len   = end - start;
    const int crows = (len < CAP_ROWS) ? len : CAP_ROWS;

    __shared__ float sm_sum[64];
    __shared__ float sm_sq [64];
    __shared__ float sm_a[64];
    __shared__ float sm_b[64];
    __shared__ uint64_t sm_mbar;

    const int chunk = t & 15;     // float4 chunk within the 64-float row
    const int rgrp  = t >> 4;     // row offset within a 24-row group (0..23)
    const int lane  = t & 31;

    const float4* __restrict__ xv = reinterpret_cast<const float4*>(x);
    float4*       __restrict__ ov = reinterpret_cast<float4*>(out);

    const uint32_t mbar = smem_u32(&sm_mbar);
    const uint32_t cache_base = smem_u32(s_cache);
    const uint32_t bytes = (uint32_t)crows * 256u;

    // ---- Init: zero accumulators, init mbarrier ----
    if (t < 64) { sm_sum[t] = 0.f; sm_sq[t] = 0.f; }
    if (t == 0) {
        asm volatile("mbarrier.init.shared.b64 [%0], %1;"
                     :: "r"(mbar), "r"(1) : "memory");
    }
    __syncthreads();

    // ---- Issue one bulk async copy (L2 evict-first: single-use lines) ----
    if (t == 0) {
        asm volatile("mbarrier.arrive.expect_tx.shared.b64 _, [%0], %1;"
                     :: "r"(mbar), "r"(bytes) : "memory");
        asm volatile(
            "{ .reg .b64 pol;\n"
            "  createpolicy.fractional.L2::evict_first.b64 pol, 1.0;\n"
            "  cp.async.bulk.shared::cluster.global.mbarrier::complete_tx::bytes.L2::cache_hint "
            "[%0], [%1], %2, [%3], pol; }"
            :: "r"(cache_base), "l"(xv + (size_t)start * 16), "r"(bytes),
               "r"(mbar) : "memory");
    }

    // ---- Wait for the copy (acquire orders following LDS) ----
    {
        uint32_t done = 0;
        while (!done) {
            asm volatile(
                "{ .reg .pred p;\n"
                "  mbarrier.try_wait.parity.acquire.cta.shared::cta.b64 p, [%1], %2, 0x989680;\n"
                "  selp.b32 %0, 1, 0, p; }"
                : "=r"(done) : "r"(mbar), "r"(0u) : "memory");
        }
    }

    // ---- Pass 1: per-feature sum / sumsq from smem ----
    float4 acc  = make_float4(0.f, 0.f, 0.f, 0.f);
    float4 accq = make_float4(0.f, 0.f, 0.f, 0.f);

    int r = rgrp;
    for (; r + 24 < crows; r += 48) {
        float4 v0 = s_cache[(r     ) * 16 + chunk];
        float4 v1 = s_cache[(r + 24) * 16 + chunk];
        acc.x += v0.x + v1.x; acc.y += v0.y + v1.y;
        acc.z += v0.z + v1.z; acc.w += v0.w + v1.w;
        accq.x = fmaf(v0.x, v0.x, fmaf(v1.x, v1.x, accq.x));
        accq.y = fmaf(v0.y, v0.y, fmaf(v1.y, v1.y, accq.y));
        accq.z = fmaf(v0.z, v0.z, fmaf(v1.z, v1.z, accq.z));
        accq.w = fmaf(v0.w, v0.w, fmaf(v1.w, v1.w, accq.w));
    }
    if (r < crows) {
        float4 v = s_cache[r * 16 + chunk];
        acc.x += v.x; acc.y += v.y; acc.z += v.z; acc.w += v.w;
        accq.x = fmaf(v.x, v.x, accq.x); accq.y = fmaf(v.y, v.y, accq.y);
        accq.z = fmaf(v.z, v.z, accq.z); accq.w = fmaf(v.w, v.w, accq.w);
    }
    // Overflow tail (rare: ~2% of segments, a few rows; correctness guard)
    for (int rr = CAP_ROWS + rgrp; rr < len; rr += 24) {
        float4 v = __ldg(&xv[(size_t)(start + rr) * 16 + chunk]);
        acc.x += v.x; acc.y += v.y; acc.z += v.z; acc.w += v.w;
        accq.x = fmaf(v.x, v.x, accq.x); accq.y = fmaf(v.y, v.y, accq.y);
        accq.z = fmaf(v.z, v.z, accq.z); accq.w = fmaf(v.w, v.w, accq.w);
    }

    // ---- Warp fold (lanes L, L^16 share chunk), then smem atomic reduce ----
    acc.x  += __shfl_xor_sync(0xffffffffu, acc.x,  16);
    acc.y  += __shfl_xor_sync(0xffffffffu, acc.y,  16);
    acc.z  += __shfl_xor_sync(0xffffffffu, acc.z,  16);
    acc.w  += __shfl_xor_sync(0xffffffffu, acc.w,  16);
    accq.x += __shfl_xor_sync(0xffffffffu, accq.x, 16);
    accq.y += __shfl_xor_sync(0xffffffffu, accq.y, 16);
    accq.z += __shfl_xor_sync(0xffffffffu, accq.z, 16);
    accq.w += __shfl_xor_sync(0xffffffffu, accq.w, 16);
    if (lane < 16) {
        atomicAdd(&sm_sum[chunk * 4 + 0], acc.x);
        atomicAdd(&sm_sum[chunk * 4 + 1], acc.y);
        atomicAdd(&sm_sum[chunk * 4 + 2], acc.z);
        atomicAdd(&sm_sum[chunk * 4 + 3], acc.w);
        atomicAdd(&sm_sq [chunk * 4 + 0], accq.x);
        atomicAdd(&sm_sq [chunk * 4 + 1], accq.y);
        atomicAdd(&sm_sq [chunk * 4 + 2], accq.z);
        atomicAdd(&sm_sq [chunk * 4 + 3], accq.w);
    }
    __syncthreads();

    // ---- Fold scale/shift per feature ----
    if (t < 64) {
        const float inv  = 1.0f / (float)len;
        const float mean = sm_sum[t] * inv;
        float var = sm_sq[t] * inv - mean * mean;
        var = fmaxf(var, 0.0f);
        const float rstd = rsqrtf(var + EPS);
        const float a = weight[t] * rstd;
        sm_a[t] = a;
        sm_b[t] = bias[t] - mean * a;
    }
    __syncthreads();

    const float4 av = reinterpret_cast<const float4*>(sm_a)[chunk];
    const float4 bv = reinterpret_cast<const float4*>(sm_b)[chunk];

    // ---- Pass 2: normalize from smem, streaming stores ----
    r = rgrp;
    for (; r + 24 < crows; r += 48) {
        float4 v0 = s_cache[(r     ) * 16 + chunk];
        float4 v1 = s_cache[(r + 24) * 16 + chunk];
        float4 w0, w1;
        w0.x = fmaf(v0.x, av.x, bv.x); w0.y = fmaf(v0.y, av.y, bv.y);
        w0.z = fmaf(v0.z, av.z, bv.z); w0.w = fmaf(v0.w, av.w, bv.w);
        w1.x = fmaf(v1.x, av.x, bv.x); w1.y = fmaf(v1.y, av.y, bv.y);
        w1.z = fmaf(v1.z, av.z, bv.z); w1.w = fmaf(v1.w, av.w, bv.w);
        stg_cs(&ov[(size_t)(start + r     ) * 16 + chunk], w0);
        stg_cs(&ov[(size_t)(start + r + 24) * 16 + chunk], w1);
    }
    if (r < crows) {
        float4 v = s_cache[r * 16 + chunk];
        float4 w;
        w.x = fmaf(v.x, av.x, bv.x); w.y = fmaf(v.y, av.y, bv.y);
        w.z = fmaf(v.z, av.z, bv.z); w.w = fmaf(v.w, av.w, bv.w);
        stg_cs(&ov[(size_t)(start + r) * 16 + chunk], w);
    }
    // Overflow tail (rare)
    for (int rr = CAP_ROWS + rgrp; rr < len; rr += 24) {
        float4 v = __ldg(&xv[(size_t)(start + rr) * 16 + chunk]);
        float4 w;
        w.x = fmaf(v.x, av.x, bv.x); w.y = fmaf(v.y, av.y, bv.y);
        w.z = fmaf(v.z, av.z, bv.z); w.w = fmaf(v.w, av.w, bv.w);
        stg_cs(&ov[(size_t)(start + rr) * 16 + chunk], w);
    }
}

extern "C" void kernel_launch(void* const* d_in, const int* in_sizes, int n_in,
                              void* d_out, int out_size)
{
    const float* x       = (const float*)d_in[0];
    const int*   offsets = (const int*)  d_in[1];
    const float* weight  = (const float*)d_in[2];
    const float* bias    = (const float*)d_in[3];
    float*       out     = (float*)d_out;

    const int S = in_sizes[1];
    const int dyn_smem = CAP_ROWS * 16 * sizeof(float4);  // 73728 B

    cudaFuncSetAttribute(seg_ln_kernel,
                         cudaFuncAttributeMaxDynamicSharedMemorySize, dyn_smem);

    seg_ln_kernel<<<S, TPB, dyn_smem>>>(x, offsets, weight, bias, out);
}

// round 16
// speedup vs baseline: 1.1742x; 1.0038x over previous
#include <cuda_runtime.h>
#include <cuda_bf16.h>
#include <cstdint>

// Segmented layer norm — converged best (R14/R15 family, final).
// inputs: [0] input f32 [N,64], [1] offsets i32 [S] (cumulative ends),
//         [2] weight f32 [64], [3] bias f32 [64] ; output f32 [N,64]
//
// One CTA per segment (S=8192). One cp.async.bulk per CTA (L2 evict-first:
// read lines are single-use) streams the segment (<=288 rows = 73728B)
// HBM->smem via mbarrier. Pass 1: per-feature sum/sumsq from smem, lane fold
// + smem atomicAdd reduce (tiny static smem -> 3 CTAs/SM for phase-staggered
// TMA/compute/store overlap). Pass 2 normalizes from smem, st.global.cs
// streaming stores. Rare >288-row overflow (~2% of segments) LDG fallback.
// TPB=384, 3 CTAs/SM (36 warps). Traffic = 1.02GB (floor); DRAM ~83% = this
// chip's measured mixed-stream ceiling for the pattern.

#define TPB 384
#define CAP_ROWS 288              // 288 rows * 256B = 73728 B dynamic smem
#define EPS 1e-5f

extern __shared__ float4 s_cache[];   // [CAP_ROWS * 16]

__device__ __forceinline__ uint32_t smem_u32(const void* p) {
    uint32_t a;
    asm("{ .reg .u64 t; cvta.to.shared.u64 t, %1; cvt.u32.u64 %0, t; }"
        : "=r"(a) : "l"(p));
    return a;
}

__device__ __forceinline__ void stg_cs(float4* p, float4 v) {
    asm volatile("st.global.cs.v4.f32 [%0], {%1, %2, %3, %4};"
                 :: "l"(p), "f"(v.x), "f"(v.y), "f"(v.z), "f"(v.w)
                 : "memory");
}

__global__ __launch_bounds__(TPB, 3) void seg_ln_kernel(
    const float* __restrict__ x,
    const int*   __restrict__ offsets,
    const float* __restrict__ weight,
    const float* __restrict__ bias,
    float*       __restrict__ out)
{
    const int s = blockIdx.x;
    const int t = threadIdx.x;

    const int start = (s == 0) ? 0 : offsets[s - 1];
    const int end   = offsets[s];
    const int len   = end - start;
    const int crows = (len < CAP_ROWS) ? len : CAP_ROWS;

    __shared__ float sm_sum[64];
    __shared__ float sm_sq [64];
    __shared__ float sm_a[64];
    __shared__ float sm_b[64];
    __shared__ uint64_t sm_mbar;

    const int chunk = t & 15;     // float4 chunk within the 64-float row
    const int rgrp  = t >> 4;     // row offset within a 24-row group (0..23)
    const int lane  = t & 31;

    const float4* __restrict__ xv = reinterpret_cast<const float4*>(x);
    float4*       __restrict__ ov = reinterpret_cast<float4*>(out);

    const uint32_t mbar = smem_u32(&sm_mbar);
    const uint32_t cache_base = smem_u32(s_cache);
    const uint32_t bytes = (uint32_t)crows * 256u;

    // ---- Init: zero accumulators, init mbarrier ----
    if (t < 64) { sm_sum[t] = 0.f; sm_sq[t] = 0.f; }
    if (t == 0) {
        asm volatile("mbarrier.init.shared.b64 [%0], %1;"
                     :: "r"(mbar), "r"(1) : "memory");
    }
    __syncthreads();

    // ---- Issue one bulk async copy (L2 evict-first: single-use lines) ----
    if (t == 0) {
        asm volatile("mbarrier.arrive.expect_tx.shared.b64 _, [%0], %1;"
                     :: "r"(mbar), "r"(bytes) : "memory");
        asm volatile(
            "{ .reg .b64 pol;\n"
            "  createpolicy.fractional.L2::evict_first.b64 pol, 1.0;\n"
            "  cp.async.bulk.shared::cluster.global.mbarrier::complete_tx::bytes.L2::cache_hint "
            "[%0], [%1], %2, [%3], pol; }"
            :: "r"(cache_base), "l"(xv + (size_t)start * 16), "r"(bytes),
               "r"(mbar) : "memory");
    }

    // ---- Wait for the copy (acquire orders following LDS) ----
    {
        uint32_t done = 0;
        while (!done) {
            asm volatile(
                "{ .reg .pred p;\n"
                "  mbarrier.try_wait.parity.acquire.cta.shared::cta.b64 p, [%1], %2, 0x989680;\n"
                "  selp.b32 %0, 1, 0, p; }"
                : "=r"(done) : "r"(mbar), "r"(0u) : "memory");
        }
    }

    // ---- Pass 1: per-feature sum / sumsq from smem ----
    float4 acc  = make_float4(0.f, 0.f, 0.f, 0.f);
    float4 accq = make_float4(0.f, 0.f, 0.f, 0.f);

    int r = rgrp;
    for (; r + 24 < crows; r += 48) {
        float4 v0 = s_cache[(r     ) * 16 + chunk];
        float4 v1 = s_cache[(r + 24) * 16 + chunk];
        acc.x += v0.x + v1.x; acc.y += v0.y + v1.y;
        acc.z += v0.z + v1.z; acc.w += v0.w + v1.w;
        accq.x = fmaf(v0.x, v0.x, fmaf(v1.x, v1.x, accq.x));
        accq.y = fmaf(v0.y, v0.y, fmaf(v1.y, v1.y, accq.y));
        accq.z = fmaf(v0.z, v0.z, fmaf(v1.z, v1.z, accq.z));
        accq.w = fmaf(v0.w, v0.w, fmaf(v1.w, v1.w, accq.w));
    }
    if (r < crows) {
        float4 v = s_cache[r * 16 + chunk];
        acc.x += v.x; acc.y += v.y; acc.z += v.z; acc.w += v.w;
        accq.x = fmaf(v.x, v.x, accq.x); accq.y = fmaf(v.y, v.y, accq.y);
        accq.z = fmaf(v.z, v.z, accq.z); accq.w = fmaf(v.w, v.w, accq.w);
    }
    // Overflow tail (rare: ~2% of segments, a few rows; correctness guard)
    for (int rr = CAP_ROWS + rgrp; rr < len; rr += 24) {
        float4 v = __ldg(&xv[(size_t)(start + rr) * 16 + chunk]);
        acc.x += v.x; acc.y += v.y; acc.z += v.z; acc.w += v.w;
        accq.x = fmaf(v.x, v.x, accq.x); accq.y = fmaf(v.y, v.y, accq.y);
        accq.z = fmaf(v.z, v.z, accq.z); accq.w = fmaf(v.w, v.w, accq.w);
    }

    // ---- Warp fold (lanes L, L^16 share chunk), then smem atomic reduce ----
    acc.x  += __shfl_xor_sync(0xffffffffu, acc.x,  16);
    acc.y  += __shfl_xor_sync(0xffffffffu, acc.y,  16);
    acc.z  += __shfl_xor_sync(0xffffffffu, acc.z,  16);
    acc.w  += __shfl_xor_sync(0xffffffffu, acc.w,  16);
    accq.x += __shfl_xor_sync(0xffffffffu, accq.x, 16);
    accq.y += __shfl_xor_sync(0xffffffffu, accq.y, 16);
    accq.z += __shfl_xor_sync(0xffffffffu, accq.z, 16);
    accq.w += __shfl_xor_sync(0xffffffffu, accq.w, 16);
    if (lane < 16) {
        atomicAdd(&sm_sum[chunk * 4 + 0], acc.x);
        atomicAdd(&sm_sum[chunk * 4 + 1], acc.y);
        atomicAdd(&sm_sum[chunk * 4 + 2], acc.z);
        atomicAdd(&sm_sum[chunk * 4 + 3], acc.w);
        atomicAdd(&sm_sq [chunk * 4 + 0], accq.x);
        atomicAdd(&sm_sq [chunk * 4 + 1], accq.y);
        atomicAdd(&sm_sq [chunk * 4 + 2], accq.z);
        atomicAdd(&sm_sq [chunk * 4 + 3], accq.w);
    }
    __syncthreads();

    // ---- Fold scale/shift per feature ----
    if (t < 64) {
        const float inv  = 1.0f / (float)len;
        const float mean = sm_sum[t] * inv;
        float var = sm_sq[t] * inv - mean * mean;
        var = fmaxf(var, 0.0f);
        const float rstd = rsqrtf(var + EPS);
        const float a = weight[t] * rstd;
        sm_a[t] = a;
        sm_b[t] = bias[t] - mean * a;
    }
    __syncthreads();

    const float4 av = reinterpret_cast<const float4*>(sm_a)[chunk];
    const float4 bv = reinterpret_cast<const float4*>(sm_b)[chunk];

    // ---- Pass 2: normalize from smem, streaming stores ----
    r = rgrp;
    for (; r + 24 < crows; r += 48) {
        float4 v0 = s_cache[(r     ) * 16 + chunk];
        float4 v1 = s_cache[(r + 24) * 16 + chunk];
        float4 w0, w1;
        w0.x = fmaf(v0.x, av.x, bv.x); w0.y = fmaf(v0.y, av.y, bv.y);
        w0.z = fmaf(v0.z, av.z, bv.z); w0.w = fmaf(v0.w, av.w, bv.w);
        w1.x = fmaf(v1.x, av.x, bv.x); w1.y = fmaf(v1.y, av.y, bv.y);
        w1.z = fmaf(v1.z, av.z, bv.z); w1.w = fmaf(v1.w, av.w, bv.w);
        stg_cs(&ov[(size_t)(start + r     ) * 16 + chunk], w0);
        stg_cs(&ov[(size_t)(start + r + 24) * 16 + chunk], w1);
    }
    if (r < crows) {
        float4 v = s_cache[r * 16 + chunk];
        float4 w;
        w.x = fmaf(v.x, av.x, bv.x); w.y = fmaf(v.y, av.y, bv.y);
        w.z = fmaf(v.z, av.z, bv.z); w.w = fmaf(v.w, av.w, bv.w);
        stg_cs(&ov[(size_t)(start + r) * 16 + chunk], w);
    }
    // Overflow tail (rare)
    for (int rr = CAP_ROWS + rgrp; rr < len; rr += 24) {
        float4 v = __ldg(&xv[(size_t)(start + rr) * 16 + chunk]);
        float4 w;
        w.x = fmaf(v.x, av.x, bv.x); w.y = fmaf(v.y, av.y, bv.y);
        w.z = fmaf(v.z, av.z, bv.z); w.w = fmaf(v.w, av.w, bv.w);
        stg_cs(&ov[(size_t)(start + rr) * 16 + chunk], w);
    }
}

extern "C" void kernel_launch(void* const* d_in, const int* in_sizes, int n_in,
                              void* d_out, int out_size)
{
    const float* x       = (const float*)d_in[0];
    const int*   offsets = (const int*)  d_in[1];
    const float* weight  = (const float*)d_in[2];
    const float* bias    = (const float*)d_in[3];
    float*       out     = (float*)d_out;

    const int S = in_sizes[1];
    const int dyn_smem = CAP_ROWS * 16 * sizeof(float4);  // 73728 B

    cudaFuncSetAttribute(seg_ln_kernel,
                         cudaFuncAttributeMaxDynamicSharedMemorySize, dyn_smem);

    seg_ln_kernel<<<S, TPB, dyn_smem>>>(x, offsets, weight, bias, out);
}